// round 11
// baseline (speedup 1.0000x reference)
#include <cuda_runtime.h>
#include <cuda_fp16.h>

#define BATCH   64
#define NATOMS  64
#define HDIM    256
#define H2      (HDIM / 2)             /* 128 half2 per row */

/* cross-CTA exchange buffers + per-graph handshake counters (zero-init) */
__device__ unsigned g_x[BATCH * 2 * 32 * H2];   /* s1 halves: [b][jh][32][128] */
__device__ float    g_rpx[BATCH * 2 * 64];      /* row partials: [b][jh][64]   */
__device__ int      g_c1[BATCH], g_c2[BATCH], g_c3[BATCH];

__device__ __forceinline__ unsigned pack_h2(float x, float y) {
    __half2 h = __floats2half2_rn(x, y);
    return *reinterpret_cast<unsigned*>(&h);
}
__device__ __forceinline__ unsigned tanh2u(unsigned x) {
    unsigned y; asm("tanh.approx.f16x2 %0, %1;" : "=r"(y) : "r"(x)); return y;
}
__device__ __forceinline__ __half2 u2h(unsigned u) {
    return *reinterpret_cast<__half2*>(&u);
}
__device__ __forceinline__ unsigned hadd2u(unsigned a, unsigned b) {
    __half2 r = __hadd2(u2h(a), u2h(b));
    return *reinterpret_cast<unsigned*>(&r);
}
__device__ __forceinline__ void cp_async16(void* smem, const void* gmem) {
    unsigned s = (unsigned)__cvta_generic_to_shared(smem);
    asm volatile("cp.async.cg.shared.global [%0], [%1], 16;" :: "r"(s), "l"(gmem));
}
__device__ __forceinline__ int ldvol(const int* p) {
    int v; asm volatile("ld.volatile.global.b32 %0, [%1];" : "=r"(v) : "l"(p)); return v;
}

/* dynamic smem layout (bytes) */
#define OFF_AB    0         /* float Ab[2][32*36]    :  9216 */
#define OFF_BB    9216      /* float Bb[2][32*264]   : 67584 */
#define OFF_S1    76800     /* unsigned s1s[64*128]  : 32768 */
#define OFF_S2    109568    /* unsigned s2s[32*129]  : 16512 */
#define OFF_W2    126080    /* float2 w2s[128]       :  1024 */
#define OFF_COLB  127104    /* float colbuf[16][32]  :  2048 */
#define OFF_RBUF  129152    /* float rbuf[64]        :   256 */
#define OFF_CFIN  129408    /* float cfin[32]        :   128 */
#define OFF_RED   129536    /* float red[64]         :   256 */
#define SMEM_TOTAL 129792

/* one GEMM pass: 32 rows x 256 cols x K=256, tf32 MMA, 2-stage cp.async */
__device__ __forceinline__ void gemm_pass(
    const float* __restrict__ Ap, const float* __restrict__ Wp,
    float* Ab, float* Bb, float (&acc)[4][4],
    int tid, int wm, int wn, int gid, int tig)
{
#pragma unroll
    for (int nt = 0; nt < 4; nt++)
#pragma unroll
        for (int q = 0; q < 4; q++) acc[nt][q] = 0.f;

    /* prologue: chunk 0 -> stage 0 */
    if (tid < 256)
        cp_async16(&Ab[(tid >> 3) * 36 + (tid & 7) * 4],
                   Ap + (tid >> 3) * HDIM + (tid & 7) * 4);
#pragma unroll
    for (int l = 0; l < 4; l++) {
        int f = tid + l * 512;
        cp_async16(&Bb[(f >> 6) * 264 + (f & 63) * 4],
                   Wp + (f >> 6) * HDIM + (f & 63) * 4);
    }
    asm volatile("cp.async.commit_group;");

    for (int kci = 0; kci < 8; kci++) {
        const int s = kci & 1;
        if (kci + 1 < 8) {
            const int kc = (kci + 1) * 32;
            const int so = s ^ 1;
            if (tid < 256)
                cp_async16(&Ab[so * 1152 + (tid >> 3) * 36 + (tid & 7) * 4],
                           Ap + (tid >> 3) * HDIM + kc + (tid & 7) * 4);
#pragma unroll
            for (int l = 0; l < 4; l++) {
                int f = tid + l * 512;
                cp_async16(&Bb[so * 8448 + (f >> 6) * 264 + (f & 63) * 4],
                           Wp + (kc + (f >> 6)) * HDIM + (f & 63) * 4);
            }
            asm volatile("cp.async.commit_group;");
            asm volatile("cp.async.wait_group 1;");
        } else {
            asm volatile("cp.async.wait_group 0;");
        }
        __syncthreads();

        const unsigned* Au = (const unsigned*)(Ab + s * 1152);
        const unsigned* Bu = (const unsigned*)(Bb + s * 8448);
#pragma unroll
        for (int ks = 0; ks < 4; ks++) {
            const int kk = ks * 8 + tig;
            const int r = wm * 16 + gid;
            unsigned a0 = Au[r * 36 + kk],       a1 = Au[(r + 8) * 36 + kk],
                     a2 = Au[r * 36 + kk + 4],   a3 = Au[(r + 8) * 36 + kk + 4];
#pragma unroll
            for (int nt = 0; nt < 4; nt++) {
                int c = wn * 32 + nt * 8 + gid;
                unsigned bf0 = Bu[(ks * 8 + tig) * 264 + c];
                unsigned bf1 = Bu[(ks * 8 + tig + 4) * 264 + c];
                asm volatile(
                    "mma.sync.aligned.m16n8k8.row.col.f32.tf32.tf32.f32 "
                    "{%0,%1,%2,%3}, {%4,%5,%6,%7}, {%8,%9}, {%0,%1,%2,%3};"
                    : "+f"(acc[nt][0]), "+f"(acc[nt][1]),
                      "+f"(acc[nt][2]), "+f"(acc[nt][3])
                    : "r"(a0), "r"(a1), "r"(a2), "r"(a3),
                      "r"(bf0), "r"(bf1));
            }
        }
        __syncthreads();
    }
}

/* ===== fully fused: GEMM + exchange + score + softmax + outputs ===== */
__global__ void __launch_bounds__(512) fused_kernel(
    const float* __restrict__ h1, const float* __restrict__ h2,
    const float* __restrict__ W1, const float* __restrict__ b1v,
    const float* __restrict__ W2, float* __restrict__ out)
{
    extern __shared__ char smem[];
    float*    Ab   = (float*)(smem + OFF_AB);
    float*    Bb   = (float*)(smem + OFF_BB);
    unsigned* s1s  = (unsigned*)(smem + OFF_S1);
    unsigned* s2s  = (unsigned*)(smem + OFF_S2);
    float2*   w2s  = (float2*)(smem + OFF_W2);
    float*    colb = (float*)(smem + OFF_COLB);   /* [16][32] */
    float*    rbuf = (float*)(smem + OFF_RBUF);
    float*    cfin = (float*)(smem + OFF_CFIN);
    float*    red  = (float*)(smem + OFF_RED);

    const int jh = blockIdx.x, gb = blockIdx.y;
    const int tid = threadIdx.x, lane = tid & 31, w = tid >> 5;
    const int wm = w >> 3, wn = w & 7;            /* 2x8 warp grid: m16 x n32 */
    const int gid = lane >> 2, tig = lane & 3;

    if (tid < 128) w2s[tid] = *(const float2*)(W2 + tid * 2);

    float acc[4][4];

    /* ---- pass 0: s1 rows [32jh, 32jh+32) of graph gb ---- */
    gemm_pass(h1 + (size_t)(gb * NATOMS + jh * 32) * HDIM, W1,
              Ab, Bb, acc, tid, wm, wn, gid, tig);
    {
        const int r = wm * 16 + gid;
        unsigned* gxo = g_x + ((gb * 2 + jh) * 32) * H2;
#pragma unroll
        for (int nt = 0; nt < 4; nt++) {
            int col = wn * 32 + nt * 8 + tig * 2;
            float2 bv = *(const float2*)(b1v + col);
            unsigned v0 = pack_h2(acc[nt][0] + bv.x, acc[nt][1] + bv.y);
            unsigned v1 = pack_h2(acc[nt][2] + bv.x, acc[nt][3] + bv.y);
            int hh = col >> 1;
            s1s[(jh * 32 + r) * 128 + hh]     = v0;
            s1s[(jh * 32 + r + 8) * 128 + hh] = v1;
            gxo[r * H2 + hh]       = v0;
            gxo[(r + 8) * H2 + hh] = v1;
        }
    }
    __threadfence();
    __syncthreads();
    if (tid == 0) atomicAdd(&g_c1[gb], 1);

    /* ---- pass 1: s2 rows [32jh, 32jh+32) (peer doesn't need these) ---- */
    gemm_pass(h2 + (size_t)(gb * NATOMS + jh * 32) * HDIM, W1 + HDIM * HDIM,
              Ab, Bb, acc, tid, wm, wn, gid, tig);
    {
        const int r = wm * 16 + gid;
#pragma unroll
        for (int nt = 0; nt < 4; nt++) {
            int col = wn * 32 + nt * 8 + tig * 2;
            int hh = col >> 1;
            s2s[r * 129 + hh]       = pack_h2(acc[nt][0], acc[nt][1]);
            s2s[(r + 8) * 129 + hh] = pack_h2(acc[nt][2], acc[nt][3]);
        }
    }

    /* ---- fetch peer s1 half ---- */
    if (tid == 0) while (ldvol(&g_c1[gb]) < 2) __nanosleep(32);
    __syncthreads();
    {
        const unsigned* px = g_x + ((gb * 2 + (1 - jh)) * 32) * H2;
        unsigned* dst = &s1s[((1 - jh) * 32) * 128];
#pragma unroll
        for (int l = 0; l < 2; l++) {
            int f = tid + l * 512;                 /* uint4 index, 1024 total */
            *(uint4*)&dst[f * 4] = *(const uint4*)(px + f * 4);
        }
    }
    __syncthreads();

    /* ---- score: R10-proven loop (warp w owns i rows 4w..4w+3) ---- */
    const unsigned* s2row = &s2s[lane * 129];
    float accA[4], accB[4];
#pragma unroll
    for (int ii = 0; ii < 4; ii++) { accA[ii] = 0.f; accB[ii] = 0.f; }

#pragma unroll 4
    for (int hh = 0; hh < 128; hh++) {
        float2 wv = w2s[hh];
        unsigned b2 = s2row[hh];
#pragma unroll
        for (int ii = 0; ii < 4; ii++) {
            unsigned a2 = s1s[(w * 4 + ii) * 128 + hh];
            unsigned th = tanh2u(hadd2u(a2, b2));
            float2 tf = __half22float2(u2h(th));
            accA[ii] = fmaf(wv.x, tf.x, accA[ii]);
            accB[ii] = fmaf(wv.y, tf.y, accB[ii]);
        }
    }

    float colacc = 0.f;
#pragma unroll
    for (int ii = 0; ii < 4; ii++) {
        float e = __expf(accA[ii] + accB[ii]);   /* bounded: no max pass */
        colacc += e;
        float rs = e;
#pragma unroll
        for (int o = 16; o > 0; o >>= 1)
            rs += __shfl_xor_sync(0xffffffffu, rs, o);
        if (lane == 0) rbuf[w * 4 + ii] = rs;
    }
    colb[w * 32 + lane] = colacc;
    __syncthreads();

    if (tid < 32) {
        float s = 0.f;
#pragma unroll
        for (int ww = 0; ww < 16; ww++) s += colb[ww * 32 + tid];
        cfin[tid] = s;                            /* complete col sums */
    }
    if (tid < 64) g_rpx[(gb * 2 + jh) * 64 + tid] = rbuf[tid];
    __threadfence();
    __syncthreads();
    if (tid == 0) {
        atomicAdd(&g_c2[gb], 1);
        while (ldvol(&g_c2[gb]) < 2) __nanosleep(32);
    }
    __syncthreads();

    /* ---- combine, normalize, write outputs ---- */
    float r = 0.f;
    if (tid < 64) {
        r = rbuf[tid] + g_rpx[(gb * 2 + (1 - jh)) * 64 + tid];
        red[tid] = r;
    }
    __syncthreads();
    if (tid < 32) {
        float v = red[tid] + red[tid + 32];
#pragma unroll
        for (int o = 16; o > 0; o >>= 1)
            v += __shfl_xor_sync(0xffffffffu, v, o);
        if (tid == 0) red[0] = v;
    }
    __syncthreads();
    float invZ = 1.f / red[0];
    if (jh == 0 && tid < 64) out[gb * 64 + tid] = r * invZ;
    if (tid < 32)
        out[BATCH * NATOMS + gb * 64 + jh * 32 + tid] = cfin[tid] * invZ;

    /* ---- reset handshake counters (last arriver) ---- */
    __syncthreads();
    if (tid == 0) {
        int old = atomicAdd(&g_c3[gb], 1);
        if (old == 1) {
            atomicExch(&g_c1[gb], 0);
            atomicExch(&g_c2[gb], 0);
            atomicExch(&g_c3[gb], 0);
        }
    }
}

/* opt-in to >48KB dynamic smem; set once at load, re-set idempotently */
namespace {
struct HxInit {
    HxInit() {
        cudaFuncSetAttribute(fused_kernel,
                             cudaFuncAttributeMaxDynamicSharedMemorySize,
                             SMEM_TOTAL);
    }
} g_hx_init;
}

extern "C" void kernel_launch(void* const* d_in, const int* in_sizes, int n_in,
                              void* d_out, int out_size)
{
    const float *h1 = nullptr, *h2 = nullptr, *W1 = nullptr,
                *b1 = nullptr, *W2 = nullptr;
    for (int idx = 0; idx < n_in; idx++) {
        int sz = in_sizes[idx];
        if (sz == BATCH * NATOMS * HDIM) {
            if (!h1) h1 = (const float*)d_in[idx];
            else if (!h2) h2 = (const float*)d_in[idx];
        } else if (sz == 2 * HDIM * HDIM) {
            W1 = (const float*)d_in[idx];
        } else if (sz == HDIM) {
            if (!b1) b1 = (const float*)d_in[idx];
            else if (!W2) W2 = (const float*)d_in[idx];
        }
    }
    float* out = (float*)d_out;

    cudaFuncSetAttribute(fused_kernel,
                         cudaFuncAttributeMaxDynamicSharedMemorySize,
                         SMEM_TOTAL);
    fused_kernel<<<dim3(2, BATCH), 512, SMEM_TOTAL>>>(h1, h2, W1, b1, W2, out);
}

// round 12
// speedup vs baseline: 1.0988x; 1.0988x over previous
#include <cuda_runtime.h>
#include <cuda_fp16.h>

#define BATCH   64
#define NATOMS  64
#define HDIM    256
#define NROWS   (2 * BATCH * NATOMS)   /* 8192 */
#define H2      (HDIM / 2)             /* 128 half2 per row */

/* s = [h1@W1[:H]+b1 ; h2@W1[H:]] packed half2 (4 MB) */
__device__ unsigned g_sh[NROWS * H2];
__device__ float g_rpx[BATCH * 2 * 64];      /* row partials: [b][jh][64] */
__device__ int   g_c2[BATCH], g_c3[BATCH];   /* handshake (zero-init)     */

__device__ __forceinline__ unsigned pack_h2(float x, float y) {
    __half2 h = __floats2half2_rn(x, y);
    return *reinterpret_cast<unsigned*>(&h);
}
__device__ __forceinline__ unsigned tanh2u(unsigned x) {
    unsigned y; asm("tanh.approx.f16x2 %0, %1;" : "=r"(y) : "r"(x)); return y;
}
__device__ __forceinline__ __half2 u2h(unsigned u) {
    return *reinterpret_cast<__half2*>(&u);
}
__device__ __forceinline__ unsigned hadd2u(unsigned a, unsigned b) {
    __half2 r = __hadd2(u2h(a), u2h(b));
    return *reinterpret_cast<unsigned*>(&r);
}
__device__ __forceinline__ void cp_async16(void* smem, const void* gmem) {
    unsigned s = (unsigned)__cvta_generic_to_shared(smem);
    asm volatile("cp.async.cg.shared.global [%0], [%1], 16;" :: "r"(s), "l"(gmem));
}
__device__ __forceinline__ int ldvol(const int* p) {
    int v; asm volatile("ld.volatile.global.b32 %0, [%1];" : "=r"(v) : "l"(p)); return v;
}

/* ===== tf32 tensor GEMM: R6/R10-proven (64x64, 128 thr, 2-stage) ===== */
__global__ void __launch_bounds__(128) gemm_kernel(
    const float* __restrict__ h1, const float* __restrict__ h2,
    const float* __restrict__ W1, const float* __restrict__ b1)
{
    __shared__ float As[2][64 * 36];   /* [row][k], pad 36 -> conflict-free */
    __shared__ float Bs[2][32 * 72];   /* [k][n],   pad 72 -> conflict-free */

    const int row0 = blockIdx.x * 64;
    const int n0   = blockIdx.y * 64;
    const bool second = (row0 >= BATCH * NATOMS);
    const float* A = second ? h2 + (row0 - BATCH * NATOMS) * HDIM
                            : h1 + row0 * HDIM;
    const float* W = W1 + (second ? HDIM * HDIM : 0);

    const int tid = threadIdx.x;
    const int lane = tid & 31, w = tid >> 5;
    const int wm = w >> 1, wn = w & 1;
    const int gid = lane >> 2, tig = lane & 3;

    int ar[4], ac[4], bk[4], bn[4];
#pragma unroll
    for (int l = 0; l < 4; l++) {
        int f = tid + l * 128;
        ar[l] = f >> 3;  ac[l] = f & 7;
        bk[l] = f >> 4;  bn[l] = f & 15;
    }

    float acc[2][4][4];
#pragma unroll
    for (int mt = 0; mt < 2; mt++)
#pragma unroll
        for (int nt = 0; nt < 4; nt++)
#pragma unroll
            for (int q = 0; q < 4; q++) acc[mt][nt][q] = 0.f;

#pragma unroll
    for (int l = 0; l < 4; l++)
        cp_async16(&As[0][ar[l] * 36 + ac[l] * 4], A + ar[l] * HDIM + ac[l] * 4);
#pragma unroll
    for (int l = 0; l < 4; l++)
        cp_async16(&Bs[0][bk[l] * 72 + bn[l] * 4], W + bk[l] * HDIM + n0 + bn[l] * 4);
    asm volatile("cp.async.commit_group;");

    for (int kci = 0; kci < 8; kci++) {
        const int s = kci & 1;
        if (kci + 1 < 8) {
            const int kc = (kci + 1) * 32;
#pragma unroll
            for (int l = 0; l < 4; l++)
                cp_async16(&As[s ^ 1][ar[l] * 36 + ac[l] * 4],
                           A + ar[l] * HDIM + kc + ac[l] * 4);
#pragma unroll
            for (int l = 0; l < 4; l++)
                cp_async16(&Bs[s ^ 1][bk[l] * 72 + bn[l] * 4],
                           W + (kc + bk[l]) * HDIM + n0 + bn[l] * 4);
            asm volatile("cp.async.commit_group;");
            asm volatile("cp.async.wait_group 1;");
        } else {
            asm volatile("cp.async.wait_group 0;");
        }
        __syncthreads();

        const unsigned* Au = (const unsigned*)As[s];
        const unsigned* Bu = (const unsigned*)Bs[s];
#pragma unroll
        for (int ks = 0; ks < 4; ks++) {
            unsigned a[2][4], bfr[4][2];
#pragma unroll
            for (int mt = 0; mt < 2; mt++) {
                int r = wm * 32 + mt * 16 + gid;
                int kk = ks * 8 + tig;
                a[mt][0] = Au[r * 36 + kk];
                a[mt][1] = Au[(r + 8) * 36 + kk];
                a[mt][2] = Au[r * 36 + kk + 4];
                a[mt][3] = Au[(r + 8) * 36 + kk + 4];
            }
#pragma unroll
            for (int nt = 0; nt < 4; nt++) {
                int c = wn * 32 + nt * 8 + gid;
                bfr[nt][0] = Bu[(ks * 8 + tig) * 72 + c];
                bfr[nt][1] = Bu[(ks * 8 + tig + 4) * 72 + c];
            }
#pragma unroll
            for (int mt = 0; mt < 2; mt++)
#pragma unroll
                for (int nt = 0; nt < 4; nt++)
                    asm volatile(
                        "mma.sync.aligned.m16n8k8.row.col.f32.tf32.tf32.f32 "
                        "{%0,%1,%2,%3}, {%4,%5,%6,%7}, {%8,%9}, {%0,%1,%2,%3};"
                        : "+f"(acc[mt][nt][0]), "+f"(acc[mt][nt][1]),
                          "+f"(acc[mt][nt][2]), "+f"(acc[mt][nt][3])
                        : "r"(a[mt][0]), "r"(a[mt][1]), "r"(a[mt][2]), "r"(a[mt][3]),
                          "r"(bfr[nt][0]), "r"(bfr[nt][1]));
        }
        __syncthreads();
    }

#if __CUDA_ARCH__ >= 900
    cudaTriggerProgrammaticLaunchCompletion();   /* let score grid launch */
#endif

#pragma unroll
    for (int mt = 0; mt < 2; mt++) {
        int r = row0 + wm * 32 + mt * 16 + gid;
#pragma unroll
        for (int nt = 0; nt < 4; nt++) {
            int col = n0 + wn * 32 + nt * 8 + tig * 2;
            float bx = 0.f, by = 0.f;
            if (!second) { float2 bv = *(const float2*)(b1 + col); bx = bv.x; by = bv.y; }
            g_sh[r * H2 + (col >> 1)]       = pack_h2(acc[mt][nt][0] + bx, acc[mt][nt][1] + by);
            g_sh[(r + 8) * H2 + (col >> 1)] = pack_h2(acc[mt][nt][2] + bx, acc[mt][nt][3] + by);
        }
    }
}

/* ===== score + finalize: R10-proven body + R11-proven handshake tail ===== */
__global__ void __launch_bounds__(512) score_kernel(const float* __restrict__ W2,
                                                    float* __restrict__ out)
{
    __shared__ unsigned s1s[64 * 128];   /* [i][hh] half2, 32 KB           */
    __shared__ unsigned s2s[32 * 129];   /* [j][hh] pad 129: conflict-free */
    __shared__ float2   w2s[128];
    __shared__ float    colbuf[16][32];
    __shared__ float    rbuf[64];
    __shared__ float    cfin[32];
    __shared__ float    red[64];

    const int jh = blockIdx.x, b = blockIdx.y;
    const int tid = threadIdx.x, lane = tid & 31, w = tid >> 5;

    if (tid < 128) w2s[tid] = *(const float2*)(W2 + tid * 2);   /* input-only: pre-sync OK */

#if __CUDA_ARCH__ >= 900
    cudaGridDependencySynchronize();     /* wait for GEMM completion+flush */
#endif

    /* s1: all 64 rows x 128 half2 = 2048 uint4 (4/thread), linear */
    const unsigned* s1g = g_sh + (b * NATOMS) * H2;
#pragma unroll
    for (int l = 0; l < 4; l++) {
        int f = tid + l * 512;
        *(uint4*)&s1s[f * 4] = *(const uint4*)(s1g + f * 4);
    }
    /* s2: 32 rows, pad-129 scalar stores (2 uint4/thread) */
    const unsigned* s2g = g_sh + (BATCH * NATOMS + b * NATOMS + jh * 32) * H2;
#pragma unroll
    for (int l = 0; l < 2; l++) {
        int f = tid + l * 512;
        int j = f >> 5, q = f & 31;
        uint4 v = *(const uint4*)(s2g + f * 4);
        unsigned* d = &s2s[j * 129 + q * 4];
        d[0] = v.x; d[1] = v.y; d[2] = v.z; d[3] = v.w;
    }
    __syncthreads();

    /* warp w owns i rows [w*4, w*4+4), lane = local j — R2/R10-proven loop */
    const unsigned* s2row = &s2s[lane * 129];
    float accA[4], accB[4];
#pragma unroll
    for (int ii = 0; ii < 4; ii++) { accA[ii] = 0.f; accB[ii] = 0.f; }

#pragma unroll 4
    for (int hh = 0; hh < 128; hh++) {
        float2 wv = w2s[hh];           /* broadcast */
        unsigned b2 = s2row[hh];       /* conflict-free */
#pragma unroll
        for (int ii = 0; ii < 4; ii++) {
            unsigned a2 = s1s[(w * 4 + ii) * 128 + hh];   /* broadcast */
            unsigned th = tanh2u(hadd2u(a2, b2));
            float2 tf = __half22float2(u2h(th));
            accA[ii] = fmaf(wv.x, tf.x, accA[ii]);
            accB[ii] = fmaf(wv.y, tf.y, accB[ii]);
        }
    }

    float colacc = 0.f;
#pragma unroll
    for (int ii = 0; ii < 4; ii++) {
        float e = __expf(accA[ii] + accB[ii]);   /* bounded: no max pass */
        colacc += e;
        float rs = e;
#pragma unroll
        for (int o = 16; o > 0; o >>= 1)
            rs += __shfl_xor_sync(0xffffffffu, rs, o);
        if (lane == 0) rbuf[w * 4 + ii] = rs;
    }
    colbuf[w][lane] = colacc;
    __syncthreads();

    if (tid < 32) {
        float s = 0.f;
#pragma unroll
        for (int ww = 0; ww < 16; ww++) s += colbuf[ww][tid];
        cfin[tid] = s;                            /* complete col sums */
    }
    if (tid < 64) g_rpx[(b * 2 + jh) * 64 + tid] = rbuf[tid];
    __threadfence();
    __syncthreads();
    if (tid == 0) {
        atomicAdd(&g_c2[b], 1);
        while (ldvol(&g_c2[b]) < 2) __nanosleep(32);
    }
    __syncthreads();

    /* combine halves, normalize, write outputs (R11-proven tail) */
    float r = 0.f;
    if (tid < 64) {
        r = rbuf[tid] + g_rpx[(b * 2 + (1 - jh)) * 64 + tid];
        red[tid] = r;
    }
    __syncthreads();
    if (tid < 32) {
        float v = red[tid] + red[tid + 32];
#pragma unroll
        for (int o = 16; o > 0; o >>= 1)
            v += __shfl_xor_sync(0xffffffffu, v, o);
        if (tid == 0) red[0] = v;
    }
    __syncthreads();
    float invZ = 1.f / red[0];
    if (jh == 0 && tid < 64) out[b * 64 + tid] = r * invZ;
    if (tid < 32)
        out[BATCH * NATOMS + b * 64 + jh * 32 + tid] = cfin[tid] * invZ;

    /* reset handshake counters (last arriver) — replay-deterministic */
    __syncthreads();
    if (tid == 0) {
        int old = atomicAdd(&g_c3[b], 1);
        if (old == 1) {
            atomicExch(&g_c2[b], 0);
            atomicExch(&g_c3[b], 0);
        }
    }
}

extern "C" void kernel_launch(void* const* d_in, const int* in_sizes, int n_in,
                              void* d_out, int out_size)
{
    const float *h1 = nullptr, *h2 = nullptr, *W1 = nullptr,
                *b1 = nullptr, *W2 = nullptr;
    for (int idx = 0; idx < n_in; idx++) {
        int sz = in_sizes[idx];
        if (sz == BATCH * NATOMS * HDIM) {
            if (!h1) h1 = (const float*)d_in[idx];
            else if (!h2) h2 = (const float*)d_in[idx];
        } else if (sz == 2 * HDIM * HDIM) {
            W1 = (const float*)d_in[idx];
        } else if (sz == HDIM) {
            if (!b1) b1 = (const float*)d_in[idx];
            else if (!W2) W2 = (const float*)d_in[idx];
        }
    }
    float* out = (float*)d_out;

    gemm_kernel<<<dim3(NROWS / 64, HDIM / 64), 128>>>(h1, h2, W1, b1);

    /* score launched with programmatic stream serialization (PDL) */
    cudaLaunchConfig_t cfg = {};
    cfg.gridDim  = dim3(2, BATCH);
    cfg.blockDim = dim3(512);
    cfg.dynamicSmemBytes = 0;
    cfg.stream = 0;
    cudaLaunchAttribute attr[1];
    attr[0].id = cudaLaunchAttributeProgrammaticStreamSerialization;
    attr[0].val.programmaticStreamSerializationAllowed = 1;
    cfg.attrs = attr;
    cfg.numAttrs = 1;
    cudaError_t e = cudaLaunchKernelEx(&cfg, score_kernel, (const float*)W2, out);
    if (e != cudaSuccess) {
        /* fallback: plain launch (identical work, stream-ordered) */
        score_kernel<<<dim3(2, BATCH), 512>>>(W2, out);
    }
}